// round 9
// baseline (speedup 1.0000x reference)
#include <cuda_runtime.h>

#define H      256
#define OUTN   200
#define DIN    20
#define TSTEPS 150
#define BETA   0.9f
#define THR    1.0f

// Transposed weights scratch: Wt[i*H + j] = W[j][i]; Wout padded to 256 cols.
// Region order gives every layer a valid overrun pad for distance-2 (8-row)
// prefetch; the tail pad covers WOt's lookahead.
#define OFF_W1 0
#define OFF_W2 5120
#define OFF_W3 (5120 + 65536)
#define OFF_W4 (5120 + 2*65536)
#define OFF_WO (5120 + 3*65536)
#define WT_TOTAL (5120 + 4*65536)
__device__ float g_Wt[WT_TOTAL + 4096];

typedef unsigned long long u64;

__device__ __forceinline__ u64 ffma2(u64 a, u64 b, u64 c) {
    u64 d;
    asm("fma.rn.f32x2 %0, %1, %2, %3;" : "=l"(d) : "l"(a), "l"(b), "l"(c));
    return d;
}
__device__ __forceinline__ u64 pack2(float w) {
    u64 d;
    asm("mov.b64 %0, {%1, %1};" : "=l"(d) : "f"(w));
    return d;
}
__device__ __forceinline__ void unpack2(u64 a, float& x, float& y) {
    asm("mov.b64 {%0, %1}, %2;" : "=f"(x), "=f"(y) : "l"(a));
}

// GEMM slice: thread computes 2 output neurons (j0, j0+128) over K inputs for
// PT packed row-pairs. JT=2 gives 2x SMEM-operand reuse. Weight prefetch uses
// a PERIOD-2 rolling buffer (cur/next, distance 8 rows) under unroll 2 so the
// rotation is fully register-renamed (zero MOVs) — R7's period-3 buffer under
// unroll 2 forced real MOV chains and regressed 50%.
// Accumulation order per (p,j) is ascending-i — bit-identical to prior rounds.
template<int K, int PT>
__device__ __forceinline__ void gemm2(const float* __restrict__ Wt,
                                      const float2* __restrict__ sb,
                                      int j0, u64* __restrict__ acc) {
#pragma unroll
    for (int q = 0; q < 2*PT; q++) acc[q] = 0ull;
    const float* __restrict__ Wa = Wt + j0;
    const float* __restrict__ Wb = Wt + j0 + 128;

    float ca[4], cb[4], na[4], nb[4];
#pragma unroll
    for (int q = 0; q < 4; q++) {
        ca[q] = Wa[q*H];       cb[q] = Wb[q*H];
        na[q] = Wa[(4+q)*H];   nb[q] = Wb[(4+q)*H];
    }
#pragma unroll 2
    for (int i = 0; i < K; i += 4) {
        float fa[4], fb[4];
#pragma unroll
        for (int q = 0; q < 4; q++) {        // prefetch group i+8 (overruns -> pad)
            fa[q] = Wa[(i+8+q)*H];
            fb[q] = Wb[(i+8+q)*H];
        }
        u64 A0 = pack2(ca[0]), A1 = pack2(ca[1]), A2 = pack2(ca[2]), A3 = pack2(ca[3]);
        u64 B0 = pack2(cb[0]), B1 = pack2(cb[1]), B2 = pack2(cb[2]), B3 = pack2(cb[3]);
#pragma unroll
        for (int p = 0; p < PT; p++) {
            const ulonglong2* s = reinterpret_cast<const ulonglong2*>(sb + p*H + i);
            ulonglong2 ab = s[0];   // pairs (i),(i+1) — already f32x2-packed
            ulonglong2 cd = s[1];   // pairs (i+2),(i+3)
            acc[p]    = ffma2(A0, ab.x, acc[p]);
            acc[p]    = ffma2(A1, ab.y, acc[p]);
            acc[p]    = ffma2(A2, cd.x, acc[p]);
            acc[p]    = ffma2(A3, cd.y, acc[p]);
            acc[PT+p] = ffma2(B0, ab.x, acc[PT+p]);
            acc[PT+p] = ffma2(B1, ab.y, acc[PT+p]);
            acc[PT+p] = ffma2(B2, cd.x, acc[PT+p]);
            acc[PT+p] = ffma2(B3, cd.y, acc[PT+p]);
        }
#pragma unroll
        for (int q = 0; q < 4; q++) { ca[q]=na[q]; cb[q]=nb[q]; na[q]=fa[q]; nb[q]=fb[q]; }
    }
}

// Leaky update (reset from PREVIOUS membrane, subtract) + spike write, 2 j's.
template<int PT>
__device__ __forceinline__ void leaky2(const u64* __restrict__ acc, float c0, float c1,
                                       float* __restrict__ m, float2* __restrict__ dst,
                                       int j0) {
#pragma unroll
    for (int js = 0; js < 2; js++) {
        float bs = js ? c1 : c0;
        int j = j0 + js*128;
#pragma unroll
        for (int p = 0; p < PT; p++) {
            float i0, i1; unpack2(acc[js*PT + p], i0, i1);
            int mi = (js*PT + p)*2;
            float a = m[mi], b = m[mi+1];
            float ra = (a > THR) ? THR : 0.f;
            float rb = (b > THR) ? THR : 0.f;
            a = BETA*a + (i0 + bs) - ra;
            b = BETA*b + (i1 + bs) - rb;
            m[mi] = a; m[mi+1] = b;
            dst[p*H + j] = make_float2(a > THR ? 1.f : 0.f, b > THR ? 1.f : 0.f);
        }
    }
}

__device__ __forceinline__ void softmax_acc(const float* __restrict__ row, int lane,
                                            float* __restrict__ accv) {
    float v[7]; float vmax = -3.0e38f;
#pragma unroll
    for (int k = 0; k < 7; k++) {
        int jj = lane + 32*k;
        v[k] = (jj < OUTN) ? row[jj] : -3.0e38f;
        vmax = fmaxf(vmax, v[k]);
    }
#pragma unroll
    for (int o = 16; o; o >>= 1) vmax = fmaxf(vmax, __shfl_xor_sync(0xffffffffu, vmax, o));
    float e[7]; float s = 0.f;
#pragma unroll
    for (int k = 0; k < 7; k++) {
        int jj = lane + 32*k;
        e[k] = (jj < OUTN) ? __expf(v[k] - vmax) : 0.f;
        s += e[k];
    }
#pragma unroll
    for (int o = 16; o; o >>= 1) s += __shfl_xor_sync(0xffffffffu, s, o);
    float inv = 1.0f / s;
#pragma unroll
    for (int k = 0; k < 7; k++) accv[k] += e[k]*inv;
}

// One independent 128-thread CTA: all 256 neurons (j0=tid, j1=tid+128),
// PT row-pairs (2*PT real batch rows starting at `start`). No dummies.
template<int PT>
__device__ __forceinline__ void run_block(
    const float* __restrict__ x,
    const float* __restrict__ b1v, const float* __restrict__ b2v,
    const float* __restrict__ b3v, const float* __restrict__ b4v,
    float* __restrict__ out, int start,
    float2* __restrict__ sb0, float2* __restrict__ sb1,
    float (* __restrict__ mo_sh)[OUTN])
{
    const int j0 = threadIdx.x;
    const int j1 = j0 + 128;
    const int wloc = j0 >> 5, lane = j0 & 31;

    float m1[4*PT], m2[4*PT], m3[4*PT], m4[4*PT], mo[4*PT];
#pragma unroll
    for (int q = 0; q < 4*PT; q++) { m1[q]=m2[q]=m3[q]=m4[q]=mo[q]=0.f; }

    const float b1a = b1v[j0], b1b = b1v[j1];
    const float b2a = b2v[j0], b2b = b2v[j1];
    const float b3a = b3v[j0], b3b = b3v[j1];
    const float b4a = b4v[j0], b4b = b4v[j1];

    // softmax rows: warp w owns row w, and row w+4 if it exists
    const int r0 = wloc;
    const int r1 = (wloc + 4 < 2*PT) ? (wloc + 4) : -1;

    float aR0[7], aR1[7];
#pragma unroll
    for (int k = 0; k < 7; k++) { aR0[k]=0.f; aR1[k]=0.f; }

    const float* W1t = g_Wt + OFF_W1;
    const float* W2t = g_Wt + OFF_W2;
    const float* W3t = g_Wt + OFF_W3;
    const float* W4t = g_Wt + OFF_W4;
    const float* WOt = g_Wt + OFF_WO;

    // x staging: thread handles up to 2 fixed (row, i) slots; pointer affine in t.
    const int elems = 2*PT*DIN;                 // 160 (PT4) or 120 (PT3)
    const int i0x = j0 % DIN,  row0 = j0 / DIN;
    const int idx1 = j0 + 128;
    const int i1x = idx1 % DIN, row1 = idx1 / DIN;
    const bool has1 = (idx1 < elems);
    const float* xp0 = x + (size_t)(start + row0)*(TSTEPS*DIN) + i0x;
    const float* xp1 = has1 ? (x + (size_t)(start + row1)*(TSTEPS*DIN) + i1x) : xp0;
    float* const sA = reinterpret_cast<float*>(sb0);
    const int off0 = ((row0 >> 1)*H + i0x)*2 + (row0 & 1);
    const int off1 = ((row1 >> 1)*H + i1x)*2 + (row1 & 1);

    float xr0 = xp0[0];
    float xr1 = xp1[0];

    u64 acc[2*PT];

    for (int t = 0; t < TSTEPS; t++) {
        // commit prefetched x_t into packed-pair layout
        sA[off0] = xr0;
        if (has1) sA[off1] = xr1;
        __syncthreads();
        // kick off x_{t+1} loads (consumed next iteration -> latency fully hidden)
        if (t + 1 < TSTEPS) {
            xr0 = xp0[(t+1)*DIN];
            xr1 = xp1[(t+1)*DIN];
        }

        gemm2<DIN,PT>(W1t, sb0, j0, acc);
        leaky2<PT>(acc, b1a, b1b, m1, sb1, j0);
        __syncthreads();
        gemm2<H,PT>(W2t, sb1, j0, acc);
        leaky2<PT>(acc, b2a, b2b, m2, sb0, j0);
        __syncthreads();
        gemm2<H,PT>(W3t, sb0, j0, acc);
        leaky2<PT>(acc, b3a, b3b, m3, sb1, j0);
        __syncthreads();
        gemm2<H,PT>(W4t, sb1, j0, acc);
        leaky2<PT>(acc, b4a, b4b, m4, sb0, j0);
        __syncthreads();
        gemm2<H,PT>(WOt, sb0, j0, acc);   // Wout cols >=200 zero-padded

        // output-layer leaky (no bias, no spike), write membranes for softmax
#pragma unroll
        for (int js = 0; js < 2; js++) {
            int j = j0 + js*128;
            if (j < OUTN) {
#pragma unroll
                for (int p = 0; p < PT; p++) {
                    float i0, i1; unpack2(acc[js*PT + p], i0, i1);
                    int mi = (js*PT + p)*2;
                    float a = mo[mi], b = mo[mi+1];
                    float ra = (a > THR) ? THR : 0.f;
                    float rb2 = (b > THR) ? THR : 0.f;
                    a = BETA*a + i0 - ra;
                    b = BETA*b + i1 - rb2;
                    mo[mi] = a; mo[mi+1] = b;
                    mo_sh[2*p  ][j] = a;
                    mo_sh[2*p+1][j] = b;
                }
            }
        }
        __syncthreads();

        if (t > 50) {
            softmax_acc(mo_sh[r0], lane, aR0);
            if (r1 >= 0) softmax_acc(mo_sh[r1], lane, aR1);
        }
        // no trailing barrier: next sb0/mo_sh writes are barrier-separated from
        // these reads (sb0 write precedes a sync; mo_sh rewrite is 6 syncs away).
    }

    // write outputs (all rows real)
    {
        size_t g = (size_t)(start + r0)*OUTN;
#pragma unroll
        for (int k = 0; k < 7; k++) {
            int jj = lane + 32*k;
            if (jj < OUTN) out[g + jj] = aR0[k];
        }
        if (r1 >= 0) {
            size_t g2 = (size_t)(start + r1)*OUTN;
#pragma unroll
            for (int k = 0; k < 7; k++) {
                int jj = lane + 32*k;
                if (jj < OUTN) out[g2 + jj] = aR1[k];
            }
        }
    }
}

__global__ void prep_weights(const float* __restrict__ W1, const float* __restrict__ W2,
                             const float* __restrict__ W3, const float* __restrict__ W4,
                             const float* __restrict__ WO) {
    int idx = blockIdx.x * blockDim.x + threadIdx.x;
    if (idx < 5120) {
        int i = idx >> 8, jj = idx & 255;
        g_Wt[OFF_W1 + idx] = W1[jj*DIN + i];
    } else if (idx < 5120 + 65536) {
        int r = idx - 5120; int i = r >> 8, jj = r & 255;
        g_Wt[OFF_W2 + r] = W2[jj*H + i];
    } else if (idx < 5120 + 2*65536) {
        int r = idx - 5120 - 65536; int i = r >> 8, jj = r & 255;
        g_Wt[OFF_W3 + r] = W3[jj*H + i];
    } else if (idx < 5120 + 3*65536) {
        int r = idx - 5120 - 2*65536; int i = r >> 8, jj = r & 255;
        g_Wt[OFF_W4 + r] = W4[jj*H + i];
    } else if (idx < WT_TOTAL) {
        int r = idx - 5120 - 3*65536; int i = r >> 8, jj = r & 255;
        g_Wt[OFF_WO + r] = (jj < OUTN) ? WO[jj*H + i] : 0.f;
    }
}

// 296 CTAs of 128 threads, 2 resident per SM (independent barrier domains).
// Blocks 0..135: PT=4 (8 rows each). Blocks 136..295: PT=3 (6 rows each).
__global__ void __launch_bounds__(128, 2)
snn_main(const float* __restrict__ x,
         const float* __restrict__ b1, const float* __restrict__ b2,
         const float* __restrict__ b3, const float* __restrict__ b4,
         float* __restrict__ out) {
    __shared__ float2 sb0[4 * H];
    __shared__ float2 sb1[4 * H];
    __shared__ float  mo_sh[8][OUTN];

    const int blk = blockIdx.x;
    if (blk < 136) {
        int start = 8 * blk;                       // 4 pairs = 8 rows
        run_block<4>(x, b1, b2, b3, b4, out, start, sb0, sb1, mo_sh);
    } else {
        int start = 1088 + 6 * (blk - 136);        // 3 pairs = 6 rows
        run_block<3>(x, b1, b2, b3, b4, out, start, sb0, sb1, mo_sh);
    }
}

extern "C" void kernel_launch(void* const* d_in, const int* in_sizes, int n_in,
                              void* d_out, int out_size) {
    const float* x  = (const float*)d_in[0];
    const float* W1 = (const float*)d_in[1];
    const float* b1 = (const float*)d_in[2];
    const float* W2 = (const float*)d_in[3];
    const float* b2 = (const float*)d_in[4];
    const float* W3 = (const float*)d_in[5];
    const float* b3 = (const float*)d_in[6];
    const float* W4 = (const float*)d_in[7];
    const float* b4 = (const float*)d_in[8];
    const float* WO = (const float*)d_in[9];
    float* out = (float*)d_out;

    prep_weights<<<(WT_TOTAL + 255) / 256, 256>>>(W1, W2, W3, W4, WO);
    snn_main<<<296, 128>>>(x, b1, b2, b3, b4, out);
}

// round 10
// speedup vs baseline: 1.0069x; 1.0069x over previous
#include <cuda_runtime.h>

#define H      256
#define OUTN   200
#define DIN    20
#define TSTEPS 150
#define BETA   0.9f
#define THR    1.0f

// Transposed weights: Wt[i*H + j] = W[j][i]; Wout padded to 256 cols.
// Region order gives every layer a valid overrun pad for distance-2 (8-row)
// prefetch; tail pad covers WOt's lookahead.
#define OFF_W1 0
#define OFF_W2 5120
#define OFF_W3 (5120 + 65536)
#define OFF_W4 (5120 + 2*65536)
#define OFF_WO (5120 + 3*65536)
#define WT_TOTAL (5120 + 4*65536)
__device__ float g_Wt[WT_TOTAL + 4096];

// dynamic smem: sb0(7*H f2) | sb1(7*H f2) | memb(5*7*H f2) | mo_sh(14*OUTN f)
#define DSMEM_BYTES ((49*H)*8 + 14*OUTN*4)

typedef unsigned long long u64;

__device__ __forceinline__ u64 ffma2(u64 a, u64 b, u64 c) {
    u64 d;
    asm("fma.rn.f32x2 %0, %1, %2, %3;" : "=l"(d) : "l"(a), "l"(b), "l"(c));
    return d;
}
__device__ __forceinline__ u64 pack2(float w) {
    u64 d;
    asm("mov.b64 %0, {%1, %1};" : "=l"(d) : "f"(w));
    return d;
}
__device__ __forceinline__ void unpack2(u64 a, float& x, float& y) {
    asm("mov.b64 {%0, %1}, %2;" : "=f"(x), "=f"(y) : "l"(a));
}
// 64-thread named barrier (per independent half-unit)
__device__ __forceinline__ void barh(int id) {
    asm volatile("bar.sync %0, 64;" :: "r"(id) : "memory");
}

// GEMM slice: thread computes 4 neurons (j = jb+64k) over K inputs for PT
// packed row-pairs. JT=4 -> 4x SMEM-operand reuse (each spike LDS.128 feeds
// 8 FFMA2). Weight prefetch: period-2 rolling buffer (cur/next, distance 8
// rows) under unroll 2 so the rotation register-renames away (R7 lesson:
// rotation period must divide the unroll factor).
// Accumulation per (k,p) is ascending-i — bit-identical to prior rounds.
template<int K, int PT>
__device__ __forceinline__ void gemm4(const float* __restrict__ Wt,
                                      const float2* __restrict__ sb,
                                      int jb, u64* __restrict__ acc) {
#pragma unroll
    for (int q = 0; q < 4*PT; q++) acc[q] = 0ull;
    const float* __restrict__ W = Wt + jb;

    float c[4][4], n[4][4];
#pragma unroll
    for (int q = 0; q < 4; q++)
#pragma unroll
        for (int k = 0; k < 4; k++) {
            c[k][q] = W[q*H + 64*k];
            n[k][q] = W[(4+q)*H + 64*k];
        }
#pragma unroll 2
    for (int i = 0; i < K; i += 4) {
        float f[4][4];
#pragma unroll
        for (int q = 0; q < 4; q++)
#pragma unroll
            for (int k = 0; k < 4; k++)         // prefetch rows i+8..i+11
                f[k][q] = W[(i+8+q)*H + 64*k];
        u64 A[4][4];
#pragma unroll
        for (int k = 0; k < 4; k++)
#pragma unroll
            for (int q = 0; q < 4; q++) A[k][q] = pack2(c[k][q]);
#pragma unroll
        for (int p = 0; p < PT; p++) {
            const ulonglong2* s = reinterpret_cast<const ulonglong2*>(sb + p*H + i);
            ulonglong2 ab = s[0];   // pairs (i),(i+1) — f32x2-packed
            ulonglong2 cd = s[1];   // pairs (i+2),(i+3)
#pragma unroll
            for (int k = 0; k < 4; k++) {
                acc[k*PT+p] = ffma2(A[k][0], ab.x, acc[k*PT+p]);
                acc[k*PT+p] = ffma2(A[k][1], ab.y, acc[k*PT+p]);
                acc[k*PT+p] = ffma2(A[k][2], cd.x, acc[k*PT+p]);
                acc[k*PT+p] = ffma2(A[k][3], cd.y, acc[k*PT+p]);
            }
        }
#pragma unroll
        for (int q = 0; q < 4; q++)
#pragma unroll
            for (int k = 0; k < 4; k++) { c[k][q] = n[k][q]; n[k][q] = f[k][q]; }
    }
}

// Leaky update (reset from PREVIOUS membrane, subtract): membranes live in
// SMEM (thread-private cells, no sync needed); spikes written to dst.
template<int PT>
__device__ __forceinline__ void leaky4(const u64* __restrict__ acc,
                                       const float* __restrict__ B,
                                       float2* __restrict__ ml,
                                       float2* __restrict__ dst, int jb) {
#pragma unroll
    for (int k = 0; k < 4; k++) {
        int j = jb + 64*k;
        float bs = B[k];
#pragma unroll
        for (int p = 0; p < PT; p++) {
            float i0, i1; unpack2(acc[k*PT+p], i0, i1);
            float2 mv = ml[p*H + j];
            float ra = (mv.x > THR) ? THR : 0.f;
            float rb = (mv.y > THR) ? THR : 0.f;
            mv.x = BETA*mv.x + (i0 + bs) - ra;
            mv.y = BETA*mv.y + (i1 + bs) - rb;
            ml[p*H + j] = mv;
            dst[p*H + j] = make_float2(mv.x > THR ? 1.f : 0.f, mv.y > THR ? 1.f : 0.f);
        }
    }
}

__device__ __forceinline__ void softmax_acc(const float* __restrict__ row, int lane,
                                            float* __restrict__ accv) {
    float v[7]; float vmax = -3.0e38f;
#pragma unroll
    for (int k = 0; k < 7; k++) {
        int jj = lane + 32*k;
        v[k] = (jj < OUTN) ? row[jj] : -3.0e38f;
        vmax = fmaxf(vmax, v[k]);
    }
#pragma unroll
    for (int o = 16; o; o >>= 1) vmax = fmaxf(vmax, __shfl_xor_sync(0xffffffffu, vmax, o));
    float e[7]; float s = 0.f;
#pragma unroll
    for (int k = 0; k < 7; k++) {
        int jj = lane + 32*k;
        e[k] = (jj < OUTN) ? __expf(v[k] - vmax) : 0.f;
        s += e[k];
    }
#pragma unroll
    for (int o = 16; o; o >>= 1) s += __shfl_xor_sync(0xffffffffu, s, o);
    float inv = 1.0f / s;
#pragma unroll
    for (int k = 0; k < 7; k++) accv[k] += e[k]*inv;
}

// One fully independent 64-thread unit: all 256 neurons (JT=4), pairs
// [POFF, POFF+PT). Own spikes, own membranes, own mo_sh rows, own barrier.
template<int PT, int POFF>
__device__ __forceinline__ void run_side(
    const float* __restrict__ x,
    const float* __restrict__ b1v, const float* __restrict__ b2v,
    const float* __restrict__ b3v, const float* __restrict__ b4v,
    float* __restrict__ out, int start, int barid,
    float2* __restrict__ sb0, float2* __restrict__ sb1,
    float2* __restrict__ memb, float* __restrict__ mo_sh)
{
    const int htid = threadIdx.x & 63;
    const int wl   = (threadIdx.x >> 5) & 1;
    const int lane = threadIdx.x & 31;
    const int jb   = htid;

    // biases for my 4 neurons per layer
    float B1[4], B2[4], B3[4], B4[4];
#pragma unroll
    for (int k = 0; k < 4; k++) {
        B1[k] = b1v[jb+64*k]; B2[k] = b2v[jb+64*k];
        B3[k] = b3v[jb+64*k]; B4[k] = b4v[jb+64*k];
    }

    // membrane layer bases (own pair columns)
    float2* M1 = memb + 0*7*H + POFF*H;
    float2* M2 = memb + 1*7*H + POFF*H;
    float2* M3 = memb + 2*7*H + POFF*H;
    float2* M4 = memb + 3*7*H + POFF*H;
    float2* M5 = memb + 4*7*H + POFF*H;

    // zero exactly my own cells (no barrier needed)
#pragma unroll
    for (int k = 0; k < 4; k++) {
        int j = jb + 64*k;
#pragma unroll
        for (int p = 0; p < PT; p++) {
            float2 z = make_float2(0.f, 0.f);
            M1[p*H+j] = z; M2[p*H+j] = z; M3[p*H+j] = z; M4[p*H+j] = z; M5[p*H+j] = z;
        }
    }

    // x staging: up to 3 fixed (row,i) slots per thread, pointer affine in t
    const int elems = 2*PT*DIN;               // 160 (PT4) or 120 (PT3)
    const float* xp[3]; int soff[3]; bool hs[3]; float xr[3];
    float* const sA = reinterpret_cast<float*>(sb0);
#pragma unroll
    for (int s = 0; s < 3; s++) {
        int idx = htid + 64*s;
        hs[s] = (idx < elems);
        int rowl = idx / DIN, ii = idx - rowl*DIN;
        int row  = 2*POFF + rowl;
        int g = start + row; if (g > 2047) g = 2047;   // dummy rows clamp
        xp[s] = hs[s] ? (x + (size_t)g*(TSTEPS*DIN) + ii) : x;
        soff[s] = ((row >> 1)*H + ii)*2 + (row & 1);
        xr[s] = xp[s][0];
    }

    float aR[PT][7];
#pragma unroll
    for (int k = 0; k < PT; k++)
#pragma unroll
        for (int q = 0; q < 7; q++) aR[k][q] = 0.f;

    const float* W1t = g_Wt + OFF_W1;
    const float* W2t = g_Wt + OFF_W2;
    const float* W3t = g_Wt + OFF_W3;
    const float* W4t = g_Wt + OFF_W4;
    const float* WOt = g_Wt + OFF_WO;

    float2* const sp0 = sb0 + POFF*H;
    float2* const sp1 = sb1 + POFF*H;

    u64 acc[4*PT];

    for (int t = 0; t < TSTEPS; t++) {
        // commit prefetched x_t
#pragma unroll
        for (int s = 0; s < 3; s++) if (hs[s]) sA[soff[s]] = xr[s];
        barh(barid);
        if (t + 1 < TSTEPS) {
#pragma unroll
            for (int s = 0; s < 3; s++) xr[s] = xp[s][(t+1)*DIN];
        }

        gemm4<DIN,PT>(W1t, sp0, jb, acc);
        leaky4<PT>(acc, B1, M1, sp1, jb);
        barh(barid);
        gemm4<H,PT>(W2t, sp1, jb, acc);
        leaky4<PT>(acc, B2, M2, sp0, jb);
        barh(barid);
        gemm4<H,PT>(W3t, sp0, jb, acc);
        leaky4<PT>(acc, B3, M3, sp1, jb);
        barh(barid);
        gemm4<H,PT>(W4t, sp1, jb, acc);
        leaky4<PT>(acc, B4, M4, sp0, jb);
        barh(barid);
        gemm4<H,PT>(WOt, sp0, jb, acc);     // Wout cols >=200 zero-padded

        // output-layer leaky (no bias, no spike) -> mo_sh rows
#pragma unroll
        for (int k = 0; k < 4; k++) {
            int j = jb + 64*k;
            if (j < OUTN) {
#pragma unroll
                for (int p = 0; p < PT; p++) {
                    float i0, i1; unpack2(acc[k*PT+p], i0, i1);
                    float2 mv = M5[p*H + j];
                    float ra = (mv.x > THR) ? THR : 0.f;
                    float rb = (mv.y > THR) ? THR : 0.f;
                    mv.x = BETA*mv.x + i0 - ra;
                    mv.y = BETA*mv.y + i1 - rb;
                    M5[p*H + j] = mv;
                    int r2 = 2*(POFF + p);
                    mo_sh[r2*OUTN + j]     = mv.x;
                    mo_sh[(r2+1)*OUTN + j] = mv.y;
                }
            }
        }
        barh(barid);

        if (t > 50) {
#pragma unroll
            for (int k = 0; k < PT; k++) {
                int r = 2*POFF + wl + 2*k;          // my warp's rows, own half only
                softmax_acc(mo_sh + r*OUTN, lane, aR[k]);
            }
        }
        // no trailing barrier: next sb0 commit and mo_sh rewrite are
        // barrier-separated from these reads.
    }

    // write outputs (guard dummy rows of the tail CTA)
#pragma unroll
    for (int k = 0; k < PT; k++) {
        int r = 2*POFF + wl + 2*k;
        int g = start + r;
        if (g < 2048) {
            size_t go = (size_t)g * OUTN;
#pragma unroll
            for (int q = 0; q < 7; q++) {
                int jj = lane + 32*q;
                if (jj < OUTN) out[go + jj] = aR[k][q];
            }
        }
    }
}

__global__ void prep_weights(const float* __restrict__ W1, const float* __restrict__ W2,
                             const float* __restrict__ W3, const float* __restrict__ W4,
                             const float* __restrict__ WO) {
    int idx = blockIdx.x * blockDim.x + threadIdx.x;
    if (idx < 5120) {
        int i = idx >> 8, jj = idx & 255;
        g_Wt[OFF_W1 + idx] = W1[jj*DIN + i];
    } else if (idx < 5120 + 65536) {
        int r = idx - 5120; int i = r >> 8, jj = r & 255;
        g_Wt[OFF_W2 + r] = W2[jj*H + i];
    } else if (idx < 5120 + 2*65536) {
        int r = idx - 5120 - 65536; int i = r >> 8, jj = r & 255;
        g_Wt[OFF_W3 + r] = W3[jj*H + i];
    } else if (idx < 5120 + 3*65536) {
        int r = idx - 5120 - 2*65536; int i = r >> 8, jj = r & 255;
        g_Wt[OFF_W4 + r] = W4[jj*H + i];
    } else if (idx < WT_TOTAL) {
        int r = idx - 5120 - 3*65536; int i = r >> 8, jj = r & 255;
        g_Wt[OFF_WO + r] = (jj < OUTN) ? WO[jj*H + i] : 0.f;
    }
}

// 147 CTAs x 128 threads, 1 CTA/SM (111.5KB dyn smem). Each CTA = two
// independent 64-thread units: threads 0-63 pairs 0-3 (PT=4), threads
// 64-127 pairs 4-6 (PT=3). CTA b owns batch rows 14b..14b+13 (tail clamps).
__global__ void __launch_bounds__(128, 1)
snn_main(const float* __restrict__ x,
         const float* __restrict__ b1, const float* __restrict__ b2,
         const float* __restrict__ b3, const float* __restrict__ b4,
         float* __restrict__ out) {
    extern __shared__ float2 ds[];
    float2* sb0  = ds;
    float2* sb1  = ds + 7*H;
    float2* memb = ds + 14*H;
    float*  mo_sh = reinterpret_cast<float*>(ds + 49*H);

    const int start = 14 * blockIdx.x;
    if (threadIdx.x < 64)
        run_side<4,0>(x, b1, b2, b3, b4, out, start, 1, sb0, sb1, memb, mo_sh);
    else
        run_side<3,4>(x, b1, b2, b3, b4, out, start, 2, sb0, sb1, memb, mo_sh);
}

extern "C" void kernel_launch(void* const* d_in, const int* in_sizes, int n_in,
                              void* d_out, int out_size) {
    const float* x  = (const float*)d_in[0];
    const float* W1 = (const float*)d_in[1];
    const float* b1 = (const float*)d_in[2];
    const float* W2 = (const float*)d_in[3];
    const float* b2 = (const float*)d_in[4];
    const float* W3 = (const float*)d_in[5];
    const float* b3 = (const float*)d_in[6];
    const float* W4 = (const float*)d_in[7];
    const float* b4 = (const float*)d_in[8];
    const float* WO = (const float*)d_in[9];
    float* out = (float*)d_out;

    prep_weights<<<(WT_TOTAL + 255) / 256, 256>>>(W1, W2, W3, W4, WO);
    cudaFuncSetAttribute(snn_main, cudaFuncAttributeMaxDynamicSharedMemorySize,
                         DSMEM_BYTES);
    snn_main<<<147, 128, DSMEM_BYTES>>>(x, b1, b2, b3, b4, out);
}

// round 11
// speedup vs baseline: 1.2004x; 1.1922x over previous
#include <cuda_runtime.h>

#define H      256
#define OUTN   200
#define DIN    20
#define TSTEPS 150
#define BETA   0.9f
#define THR    1.0f

// Transposed weights: Wt[i*H + j] = W[j][i]; Wout padded to 256 cols.
// Region order gives every layer a valid overrun pad for distance-2 (8-row)
// prefetch; tail pad covers WOt's lookahead.
#define OFF_W1 0
#define OFF_W2 5120
#define OFF_W3 (5120 + 65536)
#define OFF_W4 (5120 + 2*65536)
#define OFF_WO (5120 + 3*65536)
#define WT_TOTAL (5120 + 4*65536)
__device__ float g_Wt[WT_TOTAL + 4096];

// dynamic smem per 64-thread CTA (sized for PT=4):
//   sb0[4H f2] | sb1[4H f2] | memb[5*4H f2] | mo_sh[8*OUTN f] | aR_sh[8*OUTN f]
#define DSMEM_BYTES ((28*H)*8 + 16*OUTN*4)

typedef unsigned long long u64;

__device__ __forceinline__ u64 ffma2(u64 a, u64 b, u64 c) {
    u64 d;
    asm("fma.rn.f32x2 %0, %1, %2, %3;" : "=l"(d) : "l"(a), "l"(b), "l"(c));
    return d;
}
__device__ __forceinline__ u64 pack2(float w) {
    u64 d;
    asm("mov.b64 %0, {%1, %1};" : "=l"(d) : "f"(w));
    return d;
}
__device__ __forceinline__ void unpack2(u64 a, float& x, float& y) {
    asm("mov.b64 {%0, %1}, %2;" : "=f"(x), "=f"(y) : "l"(a));
}

// GEMM slice: thread computes 4 neurons (j = jb+64k) over K inputs for PT
// packed row-pairs. JT=4 -> each spike LDS.128 feeds 8 FFMA2. Spikes for all
// PT pairs loaded first (MLP=PT on LDS); weights packed once per k (8
// transient A regs, 16 pack2/i-group). Period-2 rolling weight prefetch
// (cur/next, distance 8 rows) under unroll 2 register-renames away.
// Accumulation per (k,p) is ascending-i — bit-identical to prior rounds.
template<int K, int PT>
__device__ __forceinline__ void gemm4(const float* __restrict__ Wt,
                                      const float2* __restrict__ sb,
                                      int jb, u64* __restrict__ acc) {
#pragma unroll
    for (int q = 0; q < 4*PT; q++) acc[q] = 0ull;
    const float* __restrict__ W = Wt + jb;

    float c[4][4], n[4][4];
#pragma unroll
    for (int q = 0; q < 4; q++)
#pragma unroll
        for (int k = 0; k < 4; k++) {
            c[k][q] = W[q*H + 64*k];
            n[k][q] = W[(4+q)*H + 64*k];
        }
#pragma unroll 2
    for (int i = 0; i < K; i += 4) {
        float f[4][4];
#pragma unroll
        for (int q = 0; q < 4; q++)
#pragma unroll
            for (int k = 0; k < 4; k++)          // prefetch rows i+8..i+11
                f[k][q] = W[(i+8+q)*H + 64*k];

        // spikes for all PT pairs up-front (broadcast LDS.128, MLP=PT)
        ulonglong2 sv[PT][2];
#pragma unroll
        for (int p = 0; p < PT; p++) {
            const ulonglong2* s = reinterpret_cast<const ulonglong2*>(sb + p*H + i);
            sv[p][0] = s[0];    // pairs (i),(i+1) — f32x2-packed
            sv[p][1] = s[1];    // pairs (i+2),(i+3)
        }
#pragma unroll
        for (int k = 0; k < 4; k++) {
            u64 A0 = pack2(c[k][0]), A1 = pack2(c[k][1]);
            u64 A2 = pack2(c[k][2]), A3 = pack2(c[k][3]);
#pragma unroll
            for (int p = 0; p < PT; p++) {
                acc[k*PT+p] = ffma2(A0, sv[p][0].x, acc[k*PT+p]);
                acc[k*PT+p] = ffma2(A1, sv[p][0].y, acc[k*PT+p]);
                acc[k*PT+p] = ffma2(A2, sv[p][1].x, acc[k*PT+p]);
                acc[k*PT+p] = ffma2(A3, sv[p][1].y, acc[k*PT+p]);
            }
        }
#pragma unroll
        for (int q = 0; q < 4; q++)
#pragma unroll
            for (int k = 0; k < 4; k++) { c[k][q] = n[k][q]; n[k][q] = f[k][q]; }
    }
}

// Leaky update (reset from PREVIOUS membrane, subtract): membranes in SMEM
// (thread-private cells, no sync needed); spikes written to dst.
template<int PT>
__device__ __forceinline__ void leaky4(const u64* __restrict__ acc,
                                       const float* __restrict__ B,
                                       float2* __restrict__ ml,
                                       float2* __restrict__ dst, int jb) {
#pragma unroll
    for (int k = 0; k < 4; k++) {
        int j = jb + 64*k;
        float bs = B[k];
#pragma unroll
        for (int p = 0; p < PT; p++) {
            float i0, i1; unpack2(acc[k*PT+p], i0, i1);
            float2 mv = ml[p*H + j];
            float ra = (mv.x > THR) ? THR : 0.f;
            float rb = (mv.y > THR) ? THR : 0.f;
            mv.x = BETA*mv.x + (i0 + bs) - ra;
            mv.y = BETA*mv.y + (i1 + bs) - rb;
            ml[p*H + j] = mv;
            dst[p*H + j] = make_float2(mv.x > THR ? 1.f : 0.f, mv.y > THR ? 1.f : 0.f);
        }
    }
}

// Softmax over one mo_sh row; accumulate into aR_sh row (own warp only).
__device__ __forceinline__ void softmax_acc_sh(const float* __restrict__ row,
                                               float* __restrict__ arow, int lane) {
    float v[7]; float vmax = -3.0e38f;
#pragma unroll
    for (int k = 0; k < 7; k++) {
        int jj = lane + 32*k;
        v[k] = (jj < OUTN) ? row[jj] : -3.0e38f;
        vmax = fmaxf(vmax, v[k]);
    }
#pragma unroll
    for (int o = 16; o; o >>= 1) vmax = fmaxf(vmax, __shfl_xor_sync(0xffffffffu, vmax, o));
    float e[7]; float s = 0.f;
#pragma unroll
    for (int k = 0; k < 7; k++) {
        int jj = lane + 32*k;
        e[k] = (jj < OUTN) ? __expf(v[k] - vmax) : 0.f;
        s += e[k];
    }
#pragma unroll
    for (int o = 16; o; o >>= 1) s += __shfl_xor_sync(0xffffffffu, s, o);
    float inv = 1.0f / s;
#pragma unroll
    for (int k = 0; k < 7; k++) {
        int jj = lane + 32*k;
        if (jj < OUTN) arow[jj] += e[k]*inv;
    }
}

// One 64-thread CTA: all 256 neurons (JT=4), PT row-pairs starting at `start`.
template<int PT>
__device__ __forceinline__ void run_unit(
    const float* __restrict__ x,
    const float* __restrict__ b1v, const float* __restrict__ b2v,
    const float* __restrict__ b3v, const float* __restrict__ b4v,
    float* __restrict__ out, int start)
{
    extern __shared__ float2 ds[];
    float2* sb0   = ds;
    float2* sb1   = ds + 4*H;
    float2* memb  = ds + 8*H;
    float*  mo_sh = reinterpret_cast<float*>(ds + 28*H);
    float*  aR_sh = mo_sh + 8*OUTN;

    const int jb   = threadIdx.x;          // 0..63
    const int wl   = jb >> 5;              // warp in unit
    const int lane = jb & 31;

    float B1[4], B2[4], B3[4], B4[4];
#pragma unroll
    for (int k = 0; k < 4; k++) {
        B1[k] = b1v[jb+64*k]; B2[k] = b2v[jb+64*k];
        B3[k] = b3v[jb+64*k]; B4[k] = b4v[jb+64*k];
    }

    float2* M1 = memb + 0*4*H;
    float2* M2 = memb + 1*4*H;
    float2* M3 = memb + 2*4*H;
    float2* M4 = memb + 3*4*H;
    float2* M5 = memb + 4*4*H;

    // zero own membrane cells + aR rows
#pragma unroll
    for (int k = 0; k < 4; k++) {
        int j = jb + 64*k;
#pragma unroll
        for (int p = 0; p < PT; p++) {
            float2 z = make_float2(0.f, 0.f);
            M1[p*H+j] = z; M2[p*H+j] = z; M3[p*H+j] = z; M4[p*H+j] = z; M5[p*H+j] = z;
        }
    }
    for (int idx = jb; idx < 2*PT*OUTN; idx += 64) aR_sh[idx] = 0.f;

    // x staging: 3 fixed (row,i) slots per thread; pointer affine in t
    const int elems = 2*PT*DIN;            // 160 (PT4) or 120 (PT3)
    const float* xp[3]; int soff[3]; bool hs[3]; float xr[3];
    float* const sA = reinterpret_cast<float*>(sb0);
#pragma unroll
    for (int s = 0; s < 3; s++) {
        int idx = jb + 64*s;
        hs[s] = (idx < elems);
        int row = idx / DIN, ii = idx - row*DIN;
        xp[s] = hs[s] ? (x + (size_t)(start + row)*(TSTEPS*DIN) + ii) : x;
        soff[s] = ((row >> 1)*H + ii)*2 + (row & 1);
        xr[s] = xp[s][0];
    }

    const float* W1t = g_Wt + OFF_W1;
    const float* W2t = g_Wt + OFF_W2;
    const float* W3t = g_Wt + OFF_W3;
    const float* W4t = g_Wt + OFF_W4;
    const float* WOt = g_Wt + OFF_WO;

    u64 acc[4*PT];

    for (int t = 0; t < TSTEPS; t++) {
        // commit prefetched x_t into packed-pair layout
#pragma unroll
        for (int s = 0; s < 3; s++) if (hs[s]) sA[soff[s]] = xr[s];
        __syncthreads();
        if (t + 1 < TSTEPS) {
#pragma unroll
            for (int s = 0; s < 3; s++) xr[s] = xp[s][(t+1)*DIN];
        }

        gemm4<DIN,PT>(W1t, sb0, jb, acc);
        leaky4<PT>(acc, B1, M1, sb1, jb);
        __syncthreads();
        gemm4<H,PT>(W2t, sb1, jb, acc);
        leaky4<PT>(acc, B2, M2, sb0, jb);
        __syncthreads();
        gemm4<H,PT>(W3t, sb0, jb, acc);
        leaky4<PT>(acc, B3, M3, sb1, jb);
        __syncthreads();
        gemm4<H,PT>(W4t, sb1, jb, acc);
        leaky4<PT>(acc, B4, M4, sb0, jb);
        __syncthreads();
        gemm4<H,PT>(WOt, sb0, jb, acc);    // Wout cols >=200 zero-padded

        // output-layer leaky (no bias, no spike) -> mo_sh rows
#pragma unroll
        for (int k = 0; k < 4; k++) {
            int j = jb + 64*k;
            if (j < OUTN) {
#pragma unroll
                for (int p = 0; p < PT; p++) {
                    float i0, i1; unpack2(acc[k*PT+p], i0, i1);
                    float2 mv = M5[p*H + j];
                    float ra = (mv.x > THR) ? THR : 0.f;
                    float rb = (mv.y > THR) ? THR : 0.f;
                    mv.x = BETA*mv.x + i0 - ra;
                    mv.y = BETA*mv.y + i1 - rb;
                    M5[p*H + j] = mv;
                    mo_sh[(2*p)*OUTN + j]   = mv.x;
                    mo_sh[(2*p+1)*OUTN + j] = mv.y;
                }
            }
        }
        __syncthreads();

        if (t > 50) {
#pragma unroll
            for (int p = 0; p < PT; p++) {
                int r = 2*p + wl;              // warp wl owns odd/even rows
                softmax_acc_sh(mo_sh + r*OUTN, aR_sh + r*OUTN, lane);
            }
        }
        // no trailing barrier: gemm5's sb0 reads and mo_sh writes are separated
        // from the next iteration's writers by the syncs above; aR rows are
        // warp-private.
    }

    __syncthreads();
    // cooperative coalesced output write (all rows real — exact cover)
    for (int idx = jb; idx < 2*PT*OUTN; idx += 64) {
        int r = idx / OUTN, jj = idx - r*OUTN;
        out[(size_t)(start + r)*OUTN + jj] = aR_sh[r*OUTN + jj];
    }
}

__global__ void prep_weights(const float* __restrict__ W1, const float* __restrict__ W2,
                             const float* __restrict__ W3, const float* __restrict__ W4,
                             const float* __restrict__ WO) {
    int idx = blockIdx.x * blockDim.x + threadIdx.x;
    if (idx < 5120) {
        int i = idx >> 8, jj = idx & 255;
        g_Wt[OFF_W1 + idx] = W1[jj*DIN + i];
    } else if (idx < 5120 + 65536) {
        int r = idx - 5120; int i = r >> 8, jj = r & 255;
        g_Wt[OFF_W2 + r] = W2[jj*H + i];
    } else if (idx < 5120 + 2*65536) {
        int r = idx - 5120 - 65536; int i = r >> 8, jj = r & 255;
        g_Wt[OFF_W3 + r] = W3[jj*H + i];
    } else if (idx < 5120 + 3*65536) {
        int r = idx - 5120 - 2*65536; int i = r >> 8, jj = r & 255;
        g_Wt[OFF_W4 + r] = W4[jj*H + i];
    } else if (idx < WT_TOTAL) {
        int r = idx - 5120 - 3*65536; int i = r >> 8, jj = r & 255;
        g_Wt[OFF_WO + r] = (jj < OUTN) ? WO[jj*H + i] : 0.f;
    }
}

// 296 independent 64-thread CTAs, 2 per SM (one wave, smem 2x70KB < 228KB).
// Blocks 0..135: PT=4 (rows 8b..8b+7). Blocks 136..295: PT=3 (6 rows each).
__global__ void __launch_bounds__(64, 2)
snn_main(const float* __restrict__ x,
         const float* __restrict__ b1, const float* __restrict__ b2,
         const float* __restrict__ b3, const float* __restrict__ b4,
         float* __restrict__ out) {
    const int blk = blockIdx.x;
    if (blk < 136)
        run_unit<4>(x, b1, b2, b3, b4, out, 8*blk);
    else
        run_unit<3>(x, b1, b2, b3, b4, out, 1088 + 6*(blk - 136));
}

extern "C" void kernel_launch(void* const* d_in, const int* in_sizes, int n_in,
                              void* d_out, int out_size) {
    const float* x  = (const float*)d_in[0];
    const float* W1 = (const float*)d_in[1];
    const float* b1 = (const float*)d_in[2];
    const float* W2 = (const float*)d_in[3];
    const float* b2 = (const float*)d_in[4];
    const float* W3 = (const float*)d_in[5];
    const float* b3 = (const float*)d_in[6];
    const float* W4 = (const float*)d_in[7];
    const float* b4 = (const float*)d_in[8];
    const float* WO = (const float*)d_in[9];
    float* out = (float*)d_out;

    prep_weights<<<(WT_TOTAL + 255) / 256, 256>>>(W1, W2, W3, W4, WO);
    cudaFuncSetAttribute(snn_main, cudaFuncAttributeMaxDynamicSharedMemorySize,
                         DSMEM_BYTES);
    snn_main<<<296, 64, DSMEM_BYTES>>>(x, b1, b2, b3, b4, out);
}

// round 14
// speedup vs baseline: 1.2044x; 1.0033x over previous
#include <cuda_runtime.h>

#define H      256
#define OUTN   200
#define DIN    20
#define TSTEPS 150
#define BETA   0.9f
#define THR    1.0f

// Transposed weights: Wt[i*H + j] = W[j][i]; Wout padded to 256 cols.
// Region order gives every layer a valid overrun pad for distance-2 (8-row)
// prefetch; tail pad covers WOt's lookahead.
#define OFF_W1 0
#define OFF_W2 5120
#define OFF_W3 (5120 + 65536)
#define OFF_W4 (5120 + 2*65536)
#define OFF_WO (5120 + 3*65536)
#define WT_TOTAL (5120 + 4*65536)
__device__ float g_Wt[WT_TOTAL + 4096];

// dynamic smem per 64-thread CTA (sized for PT=4):
//   sb0[4H f2] | sb1[4H f2] | memb[5*4H f2] | mo_sh[8*OUTN f] | aR_sh[8*OUTN f]
#define DSMEM_BYTES ((28*H)*8 + 16*OUTN*4)

typedef unsigned long long u64;

__device__ __forceinline__ u64 ffma2(u64 a, u64 b, u64 c) {
    u64 d;
    asm("fma.rn.f32x2 %0, %1, %2, %3;" : "=l"(d) : "l"(a), "l"(b), "l"(c));
    return d;
}
__device__ __forceinline__ u64 pack2(float w) {
    u64 d;
    asm("mov.b64 %0, {%1, %1};" : "=l"(d) : "f"(w));
    return d;
}
__device__ __forceinline__ void unpack2(u64 a, float& x, float& y) {
    asm("mov.b64 {%0, %1}, %2;" : "=f"(x), "=f"(y) : "l"(a));
}

// GEMM slice: thread computes 4 neurons (j = jb+64k) over K inputs for PT
// packed row-pairs. JT=4 -> each spike LDS.128 feeds 8 FFMA2. Spikes for all
// PT pairs loaded first (MLP=PT on LDS); weights packed once per k (8
// transient A regs, 16 pack2/i-group). Period-2 rolling weight prefetch
// (cur/next, distance 8 rows) under unroll 2 register-renames away.
// Accumulation per (k,p) is ascending-i — bit-identical to prior rounds.
template<int K, int PT>
__device__ __forceinline__ void gemm4(const float* __restrict__ Wt,
                                      const float2* __restrict__ sb,
                                      int jb, u64* __restrict__ acc) {
#pragma unroll
    for (int q = 0; q < 4*PT; q++) acc[q] = 0ull;
    const float* __restrict__ W = Wt + jb;

    float c[4][4], n[4][4];
#pragma unroll
    for (int q = 0; q < 4; q++)
#pragma unroll
        for (int k = 0; k < 4; k++) {
            c[k][q] = W[q*H + 64*k];
            n[k][q] = W[(4+q)*H + 64*k];
        }
#pragma unroll 2
    for (int i = 0; i < K; i += 4) {
        float f[4][4];
#pragma unroll
        for (int q = 0; q < 4; q++)
#pragma unroll
            for (int k = 0; k < 4; k++)          // prefetch rows i+8..i+11
                f[k][q] = W[(i+8+q)*H + 64*k];

        // spikes for all PT pairs up-front (broadcast LDS.128, MLP=PT)
        ulonglong2 sv[PT][2];
#pragma unroll
        for (int p = 0; p < PT; p++) {
            const ulonglong2* s = reinterpret_cast<const ulonglong2*>(sb + p*H + i);
            sv[p][0] = s[0];    // pairs (i),(i+1) — f32x2-packed
            sv[p][1] = s[1];    // pairs (i+2),(i+3)
        }
#pragma unroll
        for (int k = 0; k < 4; k++) {
            u64 A0 = pack2(c[k][0]), A1 = pack2(c[k][1]);
            u64 A2 = pack2(c[k][2]), A3 = pack2(c[k][3]);
#pragma unroll
            for (int p = 0; p < PT; p++) {
                acc[k*PT+p] = ffma2(A0, sv[p][0].x, acc[k*PT+p]);
                acc[k*PT+p] = ffma2(A1, sv[p][0].y, acc[k*PT+p]);
                acc[k*PT+p] = ffma2(A2, sv[p][1].x, acc[k*PT+p]);
                acc[k*PT+p] = ffma2(A3, sv[p][1].y, acc[k*PT+p]);
            }
        }
#pragma unroll
        for (int q = 0; q < 4; q++)
#pragma unroll
            for (int k = 0; k < 4; k++) { c[k][q] = n[k][q]; n[k][q] = f[k][q]; }
    }
}

// Leaky update (reset from PREVIOUS membrane, subtract): membranes in SMEM
// (thread-private cells, no sync needed); spikes written to dst.
template<int PT>
__device__ __forceinline__ void leaky4(const u64* __restrict__ acc,
                                       const float* __restrict__ B,
                                       float2* __restrict__ ml,
                                       float2* __restrict__ dst, int jb) {
#pragma unroll
    for (int k = 0; k < 4; k++) {
        int j = jb + 64*k;
        float bs = B[k];
#pragma unroll
        for (int p = 0; p < PT; p++) {
            float i0, i1; unpack2(acc[k*PT+p], i0, i1);
            float2 mv = ml[p*H + j];
            float ra = (mv.x > THR) ? THR : 0.f;
            float rb = (mv.y > THR) ? THR : 0.f;
            mv.x = BETA*mv.x + (i0 + bs) - ra;
            mv.y = BETA*mv.y + (i1 + bs) - rb;
            ml[p*H + j] = mv;
            dst[p*H + j] = make_float2(mv.x > THR ? 1.f : 0.f, mv.y > THR ? 1.f : 0.f);
        }
    }
}

// Softmax over one mo_sh row; accumulate into aR_sh row (own warp only).
__device__ __forceinline__ void softmax_acc_sh(const float* __restrict__ row,
                                               float* __restrict__ arow, int lane) {
    float v[7]; float vmax = -3.0e38f;
#pragma unroll
    for (int k = 0; k < 7; k++) {
        int jj = lane + 32*k;
        v[k] = (jj < OUTN) ? row[jj] : -3.0e38f;
        vmax = fmaxf(vmax, v[k]);
    }
#pragma unroll
    for (int o = 16; o; o >>= 1) vmax = fmaxf(vmax, __shfl_xor_sync(0xffffffffu, vmax, o));
    float e[7]; float s = 0.f;
#pragma unroll
    for (int k = 0; k < 7; k++) {
        int jj = lane + 32*k;
        e[k] = (jj < OUTN) ? __expf(v[k] - vmax) : 0.f;
        s += e[k];
    }
#pragma unroll
    for (int o = 16; o; o >>= 1) s += __shfl_xor_sync(0xffffffffu, s, o);
    float inv = 1.0f / s;
#pragma unroll
    for (int k = 0; k < 7; k++) {
        int jj = lane + 32*k;
        if (jj < OUTN) arow[jj] += e[k]*inv;
    }
}

// One 64-thread CTA: all 256 neurons (JT=4), PT row-pairs starting at `start`.
template<int PT>
__device__ __forceinline__ void run_unit(
    const float* __restrict__ x,
    const float* __restrict__ b1v, const float* __restrict__ b2v,
    const float* __restrict__ b3v, const float* __restrict__ b4v,
    float* __restrict__ out, int start)
{
    extern __shared__ float2 ds[];
    float2* sb0   = ds;
    float2* sb1   = ds + 4*H;
    float2* memb  = ds + 8*H;
    float*  mo_sh = reinterpret_cast<float*>(ds + 28*H);
    float*  aR_sh = mo_sh + 8*OUTN;

    const int jb   = threadIdx.x;          // 0..63
    const int wl   = jb >> 5;              // warp in unit
    const int lane = jb & 31;

    float B1[4], B2[4], B3[4], B4[4];
#pragma unroll
    for (int k = 0; k < 4; k++) {
        B1[k] = b1v[jb+64*k]; B2[k] = b2v[jb+64*k];
        B3[k] = b3v[jb+64*k]; B4[k] = b4v[jb+64*k];
    }

    float2* M1 = memb + 0*4*H;
    float2* M2 = memb + 1*4*H;
    float2* M3 = memb + 2*4*H;
    float2* M4 = memb + 3*4*H;
    float2* M5 = memb + 4*4*H;

    // zero own membrane cells + aR rows
#pragma unroll
    for (int k = 0; k < 4; k++) {
        int j = jb + 64*k;
#pragma unroll
        for (int p = 0; p < PT; p++) {
            float2 z = make_float2(0.f, 0.f);
            M1[p*H+j] = z; M2[p*H+j] = z; M3[p*H+j] = z; M4[p*H+j] = z; M5[p*H+j] = z;
        }
    }
    for (int idx = jb; idx < 2*PT*OUTN; idx += 64) aR_sh[idx] = 0.f;

    // x staging: 3 fixed (row,i) slots per thread; pointer affine in t
    const int elems = 2*PT*DIN;            // 160 (PT4) or 120 (PT3)
    const float* xp[3]; int soff[3]; bool hs[3]; float xr[3];
    float* const sA = reinterpret_cast<float*>(sb0);
#pragma unroll
    for (int s = 0; s < 3; s++) {
        int idx = jb + 64*s;
        hs[s] = (idx < elems);
        int row = idx / DIN, ii = idx - row*DIN;
        xp[s] = hs[s] ? (x + (size_t)(start + row)*(TSTEPS*DIN) + ii) : x;
        soff[s] = ((row >> 1)*H + ii)*2 + (row & 1);
        xr[s] = xp[s][0];
    }

    const float* W1t = g_Wt + OFF_W1;
    const float* W2t = g_Wt + OFF_W2;
    const float* W3t = g_Wt + OFF_W3;
    const float* W4t = g_Wt + OFF_W4;
    const float* WOt = g_Wt + OFF_WO;

    u64 acc[4*PT];

    for (int t = 0; t < TSTEPS; t++) {
        // commit prefetched x_t into packed-pair layout
#pragma unroll
        for (int s = 0; s < 3; s++) if (hs[s]) sA[soff[s]] = xr[s];
        __syncthreads();
        if (t + 1 < TSTEPS) {
#pragma unroll
            for (int s = 0; s < 3; s++) xr[s] = xp[s][(t+1)*DIN];
        }

        gemm4<DIN,PT>(W1t, sb0, jb, acc);
        leaky4<PT>(acc, B1, M1, sb1, jb);
        __syncthreads();
        gemm4<H,PT>(W2t, sb1, jb, acc);
        leaky4<PT>(acc, B2, M2, sb0, jb);
        __syncthreads();
        gemm4<H,PT>(W3t, sb0, jb, acc);
        leaky4<PT>(acc, B3, M3, sb1, jb);
        __syncthreads();
        gemm4<H,PT>(W4t, sb1, jb, acc);
        leaky4<PT>(acc, B4, M4, sb0, jb);
        __syncthreads();
        gemm4<H,PT>(WOt, sb0, jb, acc);    // Wout cols >=200 zero-padded

        // output-layer leaky (no bias, no spike) -> mo_sh rows
#pragma unroll
        for (int k = 0; k < 4; k++) {
            int j = jb + 64*k;
            if (j < OUTN) {
#pragma unroll
                for (int p = 0; p < PT; p++) {
                    float i0, i1; unpack2(acc[k*PT+p], i0, i1);
                    float2 mv = M5[p*H + j];
                    float ra = (mv.x > THR) ? THR : 0.f;
                    float rb = (mv.y > THR) ? THR : 0.f;
                    mv.x = BETA*mv.x + i0 - ra;
                    mv.y = BETA*mv.y + i1 - rb;
                    M5[p*H + j] = mv;
                    mo_sh[(2*p)*OUTN + j]   = mv.x;
                    mo_sh[(2*p+1)*OUTN + j] = mv.y;
                }
            }
        }
        __syncthreads();

        if (t > 50) {
#pragma unroll
            for (int p = 0; p < PT; p++) {
                int r = 2*p + wl;              // warp wl owns odd/even rows
                softmax_acc_sh(mo_sh + r*OUTN, aR_sh + r*OUTN, lane);
            }
        }
        // no trailing barrier: gemm5's sb0 reads and mo_sh writes are separated
        // from the next iteration's writers by the syncs above; aR rows are
        // warp-private.
    }

    __syncthreads();
    // cooperative coalesced output write (all rows real — exact cover)
    for (int idx = jb; idx < 2*PT*OUTN; idx += 64) {
        int r = idx / OUTN, jj = idx - r*OUTN;
        out[(size_t)(start + r)*OUTN + jj] = aR_sh[r*OUTN + jj];
    }
}

__global__ void prep_weights(const float* __restrict__ W1, const float* __restrict__ W2,
                             const float* __restrict__ W3, const float* __restrict__ W4,
                             const float* __restrict__ WO) {
    int idx = blockIdx.x * blockDim.x + threadIdx.x;
    if (idx < 5120) {
        int i = idx >> 8, jj = idx & 255;
        g_Wt[OFF_W1 + idx] = W1[jj*DIN + i];
    } else if (idx < 5120 + 65536) {
        int r = idx - 5120; int i = r >> 8, jj = r & 255;
        g_Wt[OFF_W2 + r] = W2[jj*H + i];
    } else if (idx < 5120 + 2*65536) {
        int r = idx - 5120 - 65536; int i = r >> 8, jj = r & 255;
        g_Wt[OFF_W3 + r] = W3[jj*H + i];
    } else if (idx < 5120 + 3*65536) {
        int r = idx - 5120 - 2*65536; int i = r >> 8, jj = r & 255;
        g_Wt[OFF_W4 + r] = W4[jj*H + i];
    } else if (idx < WT_TOTAL) {
        int r = idx - 5120 - 3*65536; int i = r >> 8, jj = r & 255;
        g_Wt[OFF_WO + r] = (jj < OUTN) ? WO[jj*H + i] : 0.f;
    }
}

// 296 independent 64-thread CTAs, 2 per SM (one wave, smem 2x70KB < 228KB).
// Blocks 0..135: PT=4 (rows 8b..8b+7). Blocks 136..295: PT=3 (6 rows each).
__global__ void __launch_bounds__(64, 2)
snn_main(const float* __restrict__ x,
         const float* __restrict__ b1, const float* __restrict__ b2,
         const float* __restrict__ b3, const float* __restrict__ b4,
         float* __restrict__ out) {
    const int blk = blockIdx.x;
    if (blk < 136)
        run_unit<4>(x, b1, b2, b3, b4, out, 8*blk);
    else
        run_unit<3>(x, b1, b2, b3, b4, out, 1088 + 6*(blk - 136));
}

extern "C" void kernel_launch(void* const* d_in, const int* in_sizes, int n_in,
                              void* d_out, int out_size) {
    const float* x  = (const float*)d_in[0];
    const float* W1 = (const float*)d_in[1];
    const float* b1 = (const float*)d_in[2];
    const float* W2 = (const float*)d_in[3];
    const float* b2 = (const float*)d_in[4];
    const float* W3 = (const float*)d_in[5];
    const float* b3 = (const float*)d_in[6];
    const float* W4 = (const float*)d_in[7];
    const float* b4 = (const float*)d_in[8];
    const float* WO = (const float*)d_in[9];
    float* out = (float*)d_out;

    prep_weights<<<(WT_TOTAL + 255) / 256, 256>>>(W1, W2, W3, W4, WO);
    cudaFuncSetAttribute(snn_main, cudaFuncAttributeMaxDynamicSharedMemorySize,
                         DSMEM_BYTES);
    snn_main<<<296, 64, DSMEM_BYTES>>>(x, b1, b2, b3, b4, out);
}

// round 15
// speedup vs baseline: 2.5501x; 2.1174x over previous
#include <cuda_runtime.h>
#include <cuda_bf16.h>

#define H      256
#define OUTN   200
#define DIN    20
#define TSTEPS 150

#define MSTR   264      // membrane row stride (floats), layers 1-4
#define M5STR  208      // layer-5 membrane stride

// dynamic smem byte offsets
#define SM_M1   0
#define SM_M2   33792
#define SM_M3   67584
#define SM_M4   101376
#define SM_M5   135168              // 32 x 208 x 4 = 26624
#define SM_SB0  161792              // spikes bf16 [32][256] = 16384
#define SM_SB1  178176
#define SM_X    194560              // x [32][20] f32 = 2560
#define SM_ACC  197120              // softmax acc [32][200] f32 = 25600
#define SM_BIAS 222720              // b1..b4 [4][256] f32 = 4096
#define SM_TOT  226816

// B-fragments: [layer(4)][kc(16)][term(3)][nt(32)][lane(32)][2] u32; +pad for prefetch overrun
__device__ __align__(16) unsigned g_Wf[393216 + 8192];
__device__ float g_W1t[DIN * H];    // W1 transposed fp32 for scalar layer 1

__device__ __forceinline__ unsigned smem_u32(const void* p) {
    unsigned a;
    asm("{ .reg .u64 t; cvta.to.shared.u64 t, %1; cvt.u32.u64 %0, t; }"
        : "=r"(a) : "l"(p));
    return a;
}
__device__ __forceinline__ void ldsm4(unsigned& a0, unsigned& a1,
                                      unsigned& a2, unsigned& a3, unsigned addr) {
    asm volatile("ldmatrix.sync.aligned.m8n8.x4.shared.b16 {%0,%1,%2,%3}, [%4];"
        : "=r"(a0), "=r"(a1), "=r"(a2), "=r"(a3) : "r"(addr));
}
__device__ __forceinline__ void mma_bf16(float* c, unsigned a0, unsigned a1,
                                         unsigned a2, unsigned a3,
                                         unsigned b0, unsigned b1) {
    asm volatile("mma.sync.aligned.m16n8k16.row.col.f32.bf16.bf16.f32 "
        "{%0,%1,%2,%3}, {%4,%5,%6,%7}, {%8,%9}, {%0,%1,%2,%3};"
        : "+f"(c[0]), "+f"(c[1]), "+f"(c[2]), "+f"(c[3])
        : "r"(a0), "r"(a1), "r"(a2), "r"(a3), "r"(b0), "r"(b1));
}

// exact-ish 3-term bf16 decomposition (w = t0+t1+t2 + eps, |eps| ~ 2^-25|w|)
__device__ __forceinline__ unsigned short bterm(float w, int term) {
    __nv_bfloat16 h0 = __float2bfloat16(w);
    if (term == 0) return *(unsigned short*)&h0;
    float r1 = w - __bfloat162float(h0);
    __nv_bfloat16 h1 = __float2bfloat16(r1);
    if (term == 1) return *(unsigned short*)&h1;
    float r2 = r1 - __bfloat162float(h1);
    __nv_bfloat16 h2 = __float2bfloat16(r2);
    return *(unsigned short*)&h2;
}

__global__ void prep(const float* __restrict__ W1, const float* __restrict__ W2,
                     const float* __restrict__ W3, const float* __restrict__ W4,
                     const float* __restrict__ WO) {
    int idx = blockIdx.x * blockDim.x + threadIdx.x;
    if (idx < 393216) {
        int layer = idx / 98304; int r = idx % 98304;
        int kc = r / 6144;  r %= 6144;
        int term = r / 2048; r %= 2048;
        int nt = r >> 6;    r &= 63;
        int lane = r >> 1,  hb = r & 1;
        int n = nt * 8 + (lane >> 2);
        int k = kc * 16 + ((lane & 3) << 1) + hb * 8;
        const float* src = (layer == 0) ? W2 : (layer == 1) ? W3 : (layer == 2) ? W4 : WO;
        int nlim = (layer == 3) ? OUTN : H;
        float w0 = (n < nlim) ? src[n * H + k]     : 0.f;
        float w1 = (n < nlim) ? src[n * H + k + 1] : 0.f;
        g_Wf[idx] = (unsigned)bterm(w0, term) | ((unsigned)bterm(w1, term) << 16);
    } else if (idx < 393216 + DIN * H) {
        int r = idx - 393216; int i = r >> 8, j = r & 255;
        g_W1t[i * H + j] = W1[j * DIN + i];
    }
}

// One hidden/out MMA layer: acc[mt][nt][4] += spikes(Sb) x W(3 bf16 terms).
// kc-level software pipeline, period-2 buffers under unroll 2.
__device__ __forceinline__ void mma_layer(float acc[2][4][4],
        const unsigned* __restrict__ Wf, unsigned sbu, int w, int lane) {
#pragma unroll
    for (int a = 0; a < 2; a++)
#pragma unroll
        for (int b = 0; b < 4; b++)
#pragma unroll
            for (int c = 0; c < 4; c++) acc[a][b][c] = 0.f;

    const unsigned* bp = Wf + (w * 4) * 64 + lane * 2;
    unsigned arow = lane & 15;
    unsigned sw   = (arow & 7) << 4;
    unsigned koff = (lane >> 4) * 16;
    unsigned a0addr = sbu + arow * 512;
    unsigned a1addr = sbu + (16 + arow) * 512;

    unsigned Ac[2][4], An[2][4];
    uint2 Bc[12], Bn[12];
    ldsm4(Ac[0][0], Ac[0][1], Ac[0][2], Ac[0][3], a0addr + (koff ^ sw));
    ldsm4(Ac[1][0], Ac[1][1], Ac[1][2], Ac[1][3], a1addr + (koff ^ sw));
#pragma unroll
    for (int q = 0; q < 12; q++)
        Bc[q] = *(const uint2*)(bp + (q >> 2) * 2048 + (q & 3) * 64);

#pragma unroll 2
    for (int kc = 0; kc < 16; kc++) {
        unsigned kb = (kc + 1) * 32 + koff;          // prefetch next kc (overruns land in pad/smem, discarded)
        ldsm4(An[0][0], An[0][1], An[0][2], An[0][3], a0addr + (kb ^ sw));
        ldsm4(An[1][0], An[1][1], An[1][2], An[1][3], a1addr + (kb ^ sw));
#pragma unroll
        for (int q = 0; q < 12; q++)
            Bn[q] = *(const uint2*)(bp + (unsigned)(((kc + 1) * 3 + (q >> 2)) * 2048 + (q & 3) * 64));
#pragma unroll
        for (int term = 0; term < 3; term++)
#pragma unroll
            for (int nt = 0; nt < 4; nt++) {
                uint2 b = Bc[term * 4 + nt];
#pragma unroll
                for (int mt = 0; mt < 2; mt++)
                    mma_bf16(acc[mt][nt], Ac[mt][0], Ac[mt][1], Ac[mt][2], Ac[mt][3], b.x, b.y);
            }
#pragma unroll
        for (int q = 0; q < 12; q++) Bc[q] = Bn[q];
#pragma unroll
        for (int mt = 0; mt < 2; mt++)
#pragma unroll
            for (int r = 0; r < 4; r++) Ac[mt][r] = An[mt][r];
    }
}

// hidden-layer epilogue: bias add, leaky (reset from PREVIOUS membrane), spike -> swizzled Sb
__device__ __forceinline__ void epi_hidden(float acc[2][4][4], float* __restrict__ mb,
        const float* __restrict__ bsh, unsigned sbo, int w, int lane) {
    int r0 = lane >> 2, cp = (lane & 3) * 2, nb = w * 32;
#pragma unroll
    for (int mt = 0; mt < 2; mt++)
#pragma unroll
        for (int nt = 0; nt < 4; nt++) {
            int col = nb + nt * 8 + cp;
            float b0 = bsh[col], b1 = bsh[col + 1];
#pragma unroll
            for (int h = 0; h < 2; h++) {
                int row = mt * 16 + r0 + h * 8;
                float i0 = acc[mt][nt][h * 2 + 0] + b0;
                float i1 = acc[mt][nt][h * 2 + 1] + b1;
                float* mp = mb + row * MSTR + col;
                float m0 = mp[0], m1 = mp[1];
                float n0 = 0.9f * m0 + i0 - (m0 > 1.f ? 1.f : 0.f);
                float n1 = 0.9f * m1 + i1 - (m1 > 1.f ? 1.f : 0.f);
                mp[0] = n0; mp[1] = n1;
                unsigned sp = (n0 > 1.f ? 0x3F80u : 0u) | (n1 > 1.f ? 0x3F800000u : 0u);
                unsigned ad = sbo + row * 512 + (((unsigned)(col * 2)) ^ ((row & 7) << 4));
                asm volatile("st.shared.b32 [%0], %1;" :: "r"(ad), "r"(sp));
            }
        }
}

// output-layer epilogue: no bias, no spike; cols >= 200 skipped
__device__ __forceinline__ void epi_out(float acc[2][4][4], float* __restrict__ mb,
                                        int w, int lane) {
    int r0 = lane >> 2, cp = (lane & 3) * 2, nb = w * 32;
#pragma unroll
    for (int mt = 0; mt < 2; mt++)
#pragma unroll
        for (int nt = 0; nt < 4; nt++) {
            int col = nb + nt * 8 + cp;
            if (col < OUTN) {
#pragma unroll
                for (int h = 0; h < 2; h++) {
                    int row = mt * 16 + r0 + h * 8;
                    float i0 = acc[mt][nt][h * 2 + 0];
                    float i1 = acc[mt][nt][h * 2 + 1];
                    float* mp = mb + row * M5STR + col;
                    float m0 = mp[0], m1 = mp[1];
                    mp[0] = 0.9f * m0 + i0 - (m0 > 1.f ? 1.f : 0.f);
                    mp[1] = 0.9f * m1 + i1 - (m1 > 1.f ? 1.f : 0.f);
                }
            }
        }
}

__global__ void __launch_bounds__(256, 1)
snn_main(const float* __restrict__ x,
         const float* __restrict__ b1, const float* __restrict__ b2,
         const float* __restrict__ b3, const float* __restrict__ b4,
         float* __restrict__ out) {
    extern __shared__ char sm[];
    float* M1f  = (float*)(sm + SM_M1);
    float* M2f  = (float*)(sm + SM_M2);
    float* M3f  = (float*)(sm + SM_M3);
    float* M4f  = (float*)(sm + SM_M4);
    float* M5f  = (float*)(sm + SM_M5);
    float* xsh  = (float*)(sm + SM_X);
    float* accs = (float*)(sm + SM_ACC);
    float* bsh  = (float*)(sm + SM_BIAS);

    const int tid  = threadIdx.x;
    const int w    = tid >> 5, lane = tid & 31;
    const int start = blockIdx.x * 32;
    const unsigned smb = smem_u32(sm);
    const unsigned SB0 = smb + SM_SB0, SB1 = smb + SM_SB1;

    // stage biases; zero membranes + softmax acc
    bsh[tid] = b1[tid]; bsh[256 + tid] = b2[tid];
    bsh[512 + tid] = b3[tid]; bsh[768 + tid] = b4[tid];
    for (int i = tid; i < (SM_SB0 / 4); i += 256) ((float*)sm)[i] = 0.f;
    for (int i = tid; i < 32 * OUTN; i += 256) accs[i] = 0.f;

    // x staging: 640 elems, 3 slots/thread, pointer affine in t
    const float* xp[3]; int soff[3]; bool hs[3]; float xr[3];
#pragma unroll
    for (int s = 0; s < 3; s++) {
        int idx = tid + 256 * s;
        hs[s] = (idx < 32 * DIN);
        int row = idx / DIN, ii = idx - row * DIN;
        xp[s] = hs[s] ? (x + (size_t)(start + row) * (TSTEPS * DIN) + ii) : x;
        soff[s] = row * DIN + ii;
        xr[s] = xp[s][0];
    }

    // layer-1 scalar weights (K=20), hoisted for all timesteps
    float wv[DIN];
#pragma unroll
    for (int i = 0; i < DIN; i++) wv[i] = g_W1t[i * H + tid];
    const float bj1 = bsh[tid];

    float acc[2][4][4];
    __syncthreads();

    for (int t = 0; t < TSTEPS; t++) {
        // commit x_t, then prefetch x_{t+1}
#pragma unroll
        for (int s = 0; s < 3; s++) if (hs[s]) xsh[soff[s]] = xr[s];
        __syncthreads();
        if (t + 1 < TSTEPS) {
#pragma unroll
            for (int s = 0; s < 3; s++) xr[s] = xp[s][(t + 1) * DIN];
        }

        // ---- layer 1, scalar fp32 (exact): thread = neuron tid, all 32 rows ----
        {
#pragma unroll 4
            for (int r = 0; r < 32; r++) {
                const float* xrow = xsh + r * DIN;
                float s = 0.f;
#pragma unroll
                for (int i = 0; i < DIN; i++) s += wv[i] * xrow[i];
                float* mp = M1f + r * MSTR + tid;
                float m = mp[0];
                float n = 0.9f * m + (s + bj1) - (m > 1.f ? 1.f : 0.f);
                mp[0] = n;
                unsigned short sv = (n > 1.f) ? (unsigned short)0x3F80 : (unsigned short)0;
                unsigned ad = SB0 + r * 512 + (((unsigned)(tid * 2)) ^ ((r & 7) << 4));
                asm volatile("st.shared.b16 [%0], %1;" :: "r"(ad), "h"(sv));
            }
        }
        __syncthreads();

        mma_layer(acc, g_Wf,          SB0, w, lane);
        epi_hidden(acc, M2f, bsh + 256, SB1, w, lane);
        __syncthreads();
        mma_layer(acc, g_Wf +  98304, SB1, w, lane);
        epi_hidden(acc, M3f, bsh + 512, SB0, w, lane);
        __syncthreads();
        mma_layer(acc, g_Wf + 196608, SB0, w, lane);
        epi_hidden(acc, M4f, bsh + 768, SB1, w, lane);
        __syncthreads();
        mma_layer(acc, g_Wf + 294912, SB1, w, lane);
        epi_out(acc, M5f, w, lane);
        __syncthreads();

        if (t > 50) {
            // warp handles rows w*4 .. w*4+3
#pragma unroll
            for (int q = 0; q < 4; q++) {
                const float* row = M5f + (w * 4 + q) * M5STR;
                float* arow = accs + (w * 4 + q) * OUTN;
                float v[7]; float vmax = -3.0e38f;
#pragma unroll
                for (int k = 0; k < 7; k++) {
                    int jj = lane + 32 * k;
                    v[k] = (jj < OUTN) ? row[jj] : -3.0e38f;
                    vmax = fmaxf(vmax, v[k]);
                }
#pragma unroll
                for (int o = 16; o; o >>= 1) vmax = fmaxf(vmax, __shfl_xor_sync(0xffffffffu, vmax, o));
                float e[7]; float ssum = 0.f;
#pragma unroll
                for (int k = 0; k < 7; k++) {
                    int jj = lane + 32 * k;
                    e[k] = (jj < OUTN) ? __expf(v[k] - vmax) : 0.f;
                    ssum += e[k];
                }
#pragma unroll
                for (int o = 16; o; o >>= 1) ssum += __shfl_xor_sync(0xffffffffu, ssum, o);
                float inv = 1.0f / ssum;
#pragma unroll
                for (int k = 0; k < 7; k++) {
                    int jj = lane + 32 * k;
                    if (jj < OUTN) arow[jj] += e[k] * inv;
                }
            }
        }
        // no extra barrier: next writes to xsh/M5/accs are ordered by the syncs above
    }

    __syncthreads();
    for (int idx = tid; idx < 32 * OUTN; idx += 256) {
        int r = idx / OUTN, c = idx - r * OUTN;
        out[(size_t)(start + r) * OUTN + c] = accs[idx];
    }
}

extern "C" void kernel_launch(void* const* d_in, const int* in_sizes, int n_in,
                              void* d_out, int out_size) {
    const float* x  = (const float*)d_in[0];
    const float* W1 = (const float*)d_in[1];
    const float* b1 = (const float*)d_in[2];
    const float* W2 = (const float*)d_in[3];
    const float* b2 = (const float*)d_in[4];
    const float* W3 = (const float*)d_in[5];
    const float* b3 = (const float*)d_in[6];
    const float* W4 = (const float*)d_in[7];
    const float* b4 = (const float*)d_in[8];
    const float* WO = (const float*)d_in[9];
    float* out = (float*)d_out;

    prep<<<(393216 + DIN * H + 255) / 256, 256>>>(W1, W2, W3, W4, WO);
    cudaFuncSetAttribute(snn_main, cudaFuncAttributeMaxDynamicSharedMemorySize, SM_TOT);
    snn_main<<<64, 256, SM_TOT>>>(x, b1, b2, b3, b4, out);
}